// round 1
// baseline (speedup 1.0000x reference)
#include <cuda_runtime.h>
#include <cuda_bf16.h>
#include <math.h>

// ---------------- problem constants ----------------
#define BB 2
#define CC 256
#define HH 256
#define WWD 256
#define TTOT 131072          // B*H*W tokens (rolled coords)
#define PIX 65536            // H*W
#define NWIN 1024
#define NH 8
#define HD 32
#define PWIN 64
#define SCALE 0.17677669529663687f
#define GN_N 1048576.0f      // 16 channels * 65536 pixels per group

// ---------------- scratch (device globals; allocation-free) ----------------
__device__ float g_qgn  [(size_t)TTOT*256]; // q path, NCHW rolled spatial
__device__ float g_ktok [(size_t)TTOT*256]; // k path, token-major [t][256]
__device__ float g_vatt [(size_t)TTOT*256]; // v, [b][win][head][p][d]
__device__ float g_qatt [(size_t)TTOT*256]; // q after SRU, same layout
__device__ float g_katt [(size_t)TTOT*256]; // k after CRU, same layout
__device__ float g_ul   [(size_t)TTOT*128]; // up(0..63) | low(64..127), token-major
__device__ float g_y1   [(size_t)TTOT*256];
__device__ float g_y2   [(size_t)TTOT*192];
__device__ float g_attout[(size_t)TTOT*256]; // attention out, token-major [t][256]
__device__ float g_wqkv_t [256*768];
__device__ float g_wsq_t  [256*128];
__device__ float g_wgwc_t [2*288*128];
__device__ float g_wpwc1_t[64*256];
__device__ float g_wpwc2_t[64*192];
__device__ float g_wout_t [256*256];
__device__ float g_gnstats[2*16*2];
__device__ float g_pool[2*512];
__device__ float g_misc[4];

// ---------------- small utility kernels ----------------
__global__ void zero_small() {
    int i = blockIdx.x*256 + threadIdx.x;
    if (i < 1024) g_pool[i] = 0.f;
    if (i < 64)   g_gnstats[i] = 0.f;
}

// out[k*N + n] = in[n*K + k]
__global__ void transpose_w(const float* __restrict__ in, float* __restrict__ out, int N, int K) {
    int i = blockIdx.x*256 + threadIdx.x;
    if (i >= N*K) return;
    int n = i % N, k = i / N;
    out[i] = in[n*K + k];
}

// zero-padded block-diagonal squeeze weight: [K=256][N=128]
__global__ void make_sq(const float* __restrict__ sq1, const float* __restrict__ sq2) {
    int i = blockIdx.x*256 + threadIdx.x;
    if (i >= 256*128) return;
    int n = i & 127, k = i >> 7;
    float v = 0.f;
    if (n < 64)  { if (k < 128)  v = sq1[n*128 + k]; }
    else         { if (k >= 128) v = sq2[(n-64)*128 + (k-128)]; }
    g_wsq_t[i] = v;
}

// gwc weights: g_wgwc_t[z][k=(kin_local*9+tap)][n] = gwc_w[(z*128+n)*288 + k]
__global__ void make_gwc(const float* __restrict__ gwc) {
    int i = blockIdx.x*256 + threadIdx.x;
    if (i >= 2*288*128) return;
    int z = i / 36864, r = i % 36864;
    int k = r >> 7, n = r & 127;
    g_wgwc_t[i] = gwc[(z*128 + n)*288 + k];
}

__global__ void sum_gnw(const float* __restrict__ gn_w) {
    __shared__ float sh[256];
    sh[threadIdx.x] = gn_w[threadIdx.x];
    __syncthreads();
    for (int st = 128; st > 0; st >>= 1) {
        if (threadIdx.x < st) sh[threadIdx.x] += sh[threadIdx.x + st];
        __syncthreads();
    }
    if (threadIdx.x == 0) g_misc[0] = sh[0];
}

// ---------------- generic 128x128x8 SGEMM ----------------
template<class AF, class EF>
__global__ __launch_bounds__(256) void sgemm_k(AF af, const float* __restrict__ Bt,
                                               int bstride, EF ef, int N, int K) {
    __shared__ float As[8][128];
    __shared__ float Bs[8][128];
    int z = blockIdx.z;
    const float* B = Bt + (size_t)z * bstride;
    int m0 = blockIdx.y << 7, n0 = blockIdx.x << 7;
    int tid = threadIdx.x;
    int r0 = (tid >> 4) << 3, c0 = (tid & 15) << 3;
    float acc[8][8];
#pragma unroll
    for (int i = 0; i < 8; i++)
#pragma unroll
        for (int j = 0; j < 8; j++) acc[i][j] = 0.f;

    for (int k0 = 0; k0 < K; k0 += 8) {
#pragma unroll
        for (int i = 0; i < 4; i++) {
            int idx = (i << 8) + tid;
            int rr = idx & 127, kk = idx >> 7;
            As[kk][rr] = af(m0 + rr, k0 + kk, z);
        }
#pragma unroll
        for (int i = 0; i < 4; i++) {
            int idx = (i << 8) + tid;
            int cc = idx & 127, kk = idx >> 7;
            int n = n0 + cc;
            Bs[kk][cc] = (n < N) ? B[(size_t)(k0 + kk)*N + n] : 0.f;
        }
        __syncthreads();
#pragma unroll
        for (int kk = 0; kk < 8; kk++) {
            float a[8], bb[8];
#pragma unroll
            for (int i = 0; i < 8; i++) a[i]  = As[kk][r0 + i];
#pragma unroll
            for (int j = 0; j < 8; j++) bb[j] = Bs[kk][c0 + j];
#pragma unroll
            for (int i = 0; i < 8; i++)
#pragma unroll
                for (int j = 0; j < 8; j++) acc[i][j] += a[i]*bb[j];
        }
        __syncthreads();
    }
#pragma unroll
    for (int i = 0; i < 8; i++) {
        int m = m0 + r0 + i;
#pragma unroll
        for (int j = 0; j < 8; j++) {
            int n = n0 + c0 + j;
            if (n < N) ef(m, n, z, acc[i][j]);
        }
    }
}

// ---------------- A loaders ----------------
struct AQKV {
    const float* x;
    __device__ float operator()(int t, int k, int z) const {
        int b = t >> 16, pixi = t & 65535;
        int hr = pixi >> 8, wr = pixi & 255;
        return x[(size_t)((b << 8) + k)*65536 + (((hr + 4) & 255) << 8) + ((wr + 4) & 255)];
    }
};
struct AKtok {
    __device__ float operator()(int t, int k, int z) const { return g_ktok[(size_t)t*256 + k]; }
};
struct AUp {
    __device__ float operator()(int t, int k, int z) const { return g_ul[(size_t)t*128 + k]; }
};
struct ALow {
    __device__ float operator()(int t, int k, int z) const { return g_ul[(size_t)t*128 + 64 + k]; }
};
struct AAtt {
    __device__ float operator()(int t, int k, int z) const { return g_attout[(size_t)t*256 + k]; }
};
// implicit im2col for the grouped 3x3 conv over 'up' (cols 0..63 of g_ul)
struct AConv {
    __device__ float operator()(int t, int k, int z) const {
        int kl = k / 9;                 // 0..31
        int tap = k - kl*9;
        int kin = (z << 5) + kl;
        int dy = tap/3 - 1, dx = tap - (tap/3)*3 - 1;
        int b = t >> 16, pixi = t & 65535;
        int hr = (pixi >> 8) + dy, wr = (pixi & 255) + dx;
        if ((unsigned)hr > 255u || (unsigned)wr > 255u) return 0.f;
        return g_ul[(size_t)((b << 16) + (hr << 8) + wr)*128 + kin];
    }
};

// ---------------- epilogues ----------------
struct EQKV {
    const float* bias;
    __device__ void operator()(int t, int n, int z, float v) const {
        v += bias[n];
        int b = t >> 16, pixi = t & 65535;
        if (n < 256) {
            g_qgn[(size_t)((b << 8) + n)*65536 + pixi] = v;
        } else if (n < 512) {
            g_ktok[(size_t)t*256 + (n - 256)] = v;
        } else {
            int c = n - 512;
            int hr = pixi >> 8, wr = pixi & 255;
            int win = ((hr >> 3) << 5) + (wr >> 3);
            int p = ((hr & 7) << 3) + (wr & 7);
            g_vatt[((size_t)((b << 10) + win)*8 + (c >> 5))*2048 + p*32 + (c & 31)] = v;
        }
    }
};
struct EUL {
    __device__ void operator()(int t, int n, int z, float v) const { g_ul[(size_t)t*128 + n] = v; }
};
struct EY1 {
    const float* bias;
    __device__ void operator()(int t, int n, int z, float v) const {
        int c = (z << 7) + n;
        g_y1[(size_t)t*256 + c] = v + bias[c];
    }
};
struct EAddY1 {
    __device__ void operator()(int t, int n, int z, float v) const { g_y1[(size_t)t*256 + n] += v; }
};
struct EY2 {
    __device__ void operator()(int t, int n, int z, float v) const { g_y2[(size_t)t*192 + n] = v; }
};
struct EOut {
    const float* bias; float* out;
    __device__ void operator()(int t, int n, int z, float v) const {
        int b = t >> 16, pixi = t & 65535;
        int hr = pixi >> 8, wr = pixi & 255;
        out[(size_t)((b << 8) + n)*65536 + (((hr + 4) & 255) << 8) + ((wr + 4) & 255)] = v + bias[n];
    }
};

// ---------------- GroupNorm stats ----------------
__global__ void gn_stats() {
    int bx = blockIdx.x;            // 0..511 : one channel of one batch
    int b = bx >> 8, c = bx & 255;
    const float* p = g_qgn + (size_t)((b << 8) + c)*65536;
    float s = 0.f, s2 = 0.f;
    for (int i = threadIdx.x; i < 65536; i += 256) {
        float v = p[i];
        s += v; s2 += v*v;
    }
    __shared__ float sh[512];
    sh[threadIdx.x] = s; sh[256 + threadIdx.x] = s2;
    __syncthreads();
    for (int st = 128; st > 0; st >>= 1) {
        if (threadIdx.x < st) {
            sh[threadIdx.x] += sh[threadIdx.x + st];
            sh[256 + threadIdx.x] += sh[256 + threadIdx.x + st];
        }
        __syncthreads();
    }
    if (threadIdx.x == 0) {
        int g = c >> 4;
        atomicAdd(&g_gnstats[((b << 4) + g)*2],     sh[0]);
        atomicAdd(&g_gnstats[((b << 4) + g)*2 + 1], sh[256]);
    }
}

// ---------------- SRU per window (transpose NCHW -> [win][head][p][d] via smem) ----------------
__global__ void sru_win(const float* __restrict__ gn_w, const float* __restrict__ gn_b) {
    extern __shared__ float sm[];
    float* s   = sm;                 // 64*257 floats
    float* gnA = sm + 64*257;
    float* gnB = gnA + 256;
    float* wg  = gnB + 256;
    int blk = blockIdx.x, b = blk >> 10, win = blk & 1023;
    int wy = win >> 5, wx = win & 31;
    int tid = threadIdx.x;

    if (tid < 256) {
        int c = tid, g = c >> 4;
        float mean = g_gnstats[((b << 4) + g)*2] / GN_N;
        float var  = g_gnstats[((b << 4) + g)*2 + 1] / GN_N - mean*mean;
        float rstd = rsqrtf(var + 1e-5f);
        float w = gn_w[c];
        gnA[c] = rstd * w;
        gnB[c] = gn_b[c] - mean * rstd * w;
        wg[c]  = w / g_misc[0];
    }
    const float* src = g_qgn + (size_t)b*256*65536;
    for (int idx = tid; idx < 16384; idx += 256) {
        int c = idx >> 6, p = idx & 63;
        int hr = (wy << 3) + (p >> 3), wr = (wx << 3) + (p & 7);
        s[p*257 + c] = src[(size_t)c*65536 + (hr << 8) + wr];
    }
    __syncthreads();
    for (int idx = tid; idx < 8192; idx += 256) {
        int c = idx & 127, p = idx >> 7;
        int c2 = c + 128;
        float x1 = s[p*257 + c], x2 = s[p*257 + c2];
        float gn1 = x1*gnA[c] + gnB[c];
        float gn2 = x2*gnA[c2] + gnB[c2];
        float rw1 = 1.0f/(1.0f + expf(-gn1*wg[c]));
        float rw2 = 1.0f/(1.0f + expf(-gn2*wg[c2]));
        float w11 = rw1 > 0.5f ? 1.0f : rw1, w21 = rw1 > 0.5f ? 0.0f : rw1;
        float w12 = rw2 > 0.5f ? 1.0f : rw2, w22 = rw2 > 0.5f ? 0.0f : rw2;
        s[p*257 + c]  = w11*x1 + w22*x2;
        s[p*257 + c2] = w12*x2 + w21*x1;
    }
    __syncthreads();
    float* dst = g_qatt + (size_t)blk*16384;
    for (int idx = tid; idx < 16384; idx += 256) {
        int head = idx >> 11, p = (idx >> 5) & 63, d = idx & 31;
        dst[idx] = s[p*257 + (head << 5) + d];
    }
}

// ---------------- CRU pooling / softmax / combine ----------------
__global__ void pool_kernel() {
    int t0 = blockIdx.x * 256;
    int b = t0 >> 16;
    int tid = threadIdx.x;
    float a1 = 0.f, a2 = 0.f, a3 = 0.f;
    for (int t = t0; t < t0 + 256; t++) {
        a1 += g_y1[(size_t)t*256 + tid];
        if (tid < 192) a2 += g_y2[(size_t)t*192 + tid];
        if (tid < 64)  a3 += g_ul[(size_t)t*128 + 64 + tid];
    }
    atomicAdd(&g_pool[(b << 9) + tid], a1);
    if (tid < 192) atomicAdd(&g_pool[(b << 9) + 256 + tid], a2);
    if (tid < 64)  atomicAdd(&g_pool[(b << 9) + 448 + tid], a3);
}

__global__ void softmax512() {
    int b = blockIdx.x, t = threadIdx.x;
    __shared__ float sh[512];
    float v = g_pool[(b << 9) + t] * (1.0f/65536.0f);
    sh[t] = v;
    __syncthreads();
    for (int st = 256; st > 0; st >>= 1) { if (t < st) sh[t] = fmaxf(sh[t], sh[t + st]); __syncthreads(); }
    float mx = sh[0];
    __syncthreads();
    float e = expf(v - mx);
    sh[t] = e;
    __syncthreads();
    for (int st = 256; st > 0; st >>= 1) { if (t < st) sh[t] += sh[t + st]; __syncthreads(); }
    float sum = sh[0];
    __syncthreads();
    g_pool[(b << 9) + t] = e / sum;
}

__global__ void cru_combine() {
    int i = blockIdx.x*256 + threadIdx.x;          // < TTOT*256
    int t = i >> 8, c = i & 255;
    int b = t >> 16, pixi = t & 65535;
    float y1 = g_y1[i];
    float y2v = (c < 192) ? g_y2[(size_t)t*192 + c] : g_ul[(size_t)t*128 + 64 + (c - 192)];
    float s1 = g_pool[(b << 9) + c], s2 = g_pool[(b << 9) + 256 + c];
    float v = s1*y1 + s2*y2v;
    int hr = pixi >> 8, wr = pixi & 255;
    int win = ((hr >> 3) << 5) + (wr >> 3);
    int p = ((hr & 7) << 3) + (wr & 7);
    g_katt[((size_t)((b << 10) + win)*8 + (c >> 5))*2048 + p*32 + (c & 31)] = v;
}

// ---------------- windowed attention ----------------
__global__ __launch_bounds__(64) void attn(const float* __restrict__ rel_pos) {
    int win = blockIdx.x, h = blockIdx.y, b = blockIdx.z;
    __shared__ float ksh[2048], vsh[2048], rp[225];
    size_t base = ((size_t)((b << 10) + win)*8 + h)*2048;
    const float* kin = g_katt + base;
    const float* vin = g_vatt + base;
    const float* qin = g_qatt + base;
    int tid = threadIdx.x;
    for (int i = tid; i < 2048; i += 64) { ksh[i] = kin[i]; vsh[i] = vin[i]; }
    for (int i = tid; i < 225; i += 64) rp[i] = rel_pos[h*225 + i];
    __syncthreads();

    float q[32];
#pragma unroll
    for (int d = 0; d < 32; d++) q[d] = qin[tid*32 + d];
    int ph = tid >> 3, pw = tid & 7;
    bool lr = (win >> 5) == 31, lc = (win & 31) == 31;

    float s[64];
#pragma unroll
    for (int qi = 0; qi < 64; qi++) {
        float dot = 0.f;
#pragma unroll
        for (int d = 0; d < 32; d++) dot += q[d]*ksh[qi*32 + d];
        int qh = qi >> 3, qw = qi & 7;
        float val = dot*SCALE + rp[(ph - qh + 7)*15 + (pw - qw + 7)];
        if ((lr && ((ph < 4) != (qh < 4))) || (lc && ((pw < 4) != (qw < 4)))) val = -1e30f;
        s[qi] = val;
    }
    float mx = -1e30f;
#pragma unroll
    for (int qi = 0; qi < 64; qi++) mx = fmaxf(mx, s[qi]);
    float sum = 0.f;
#pragma unroll
    for (int qi = 0; qi < 64; qi++) { s[qi] = expf(s[qi] - mx); sum += s[qi]; }
    float inv = 1.0f / sum;
    float acc[32];
#pragma unroll
    for (int d = 0; d < 32; d++) acc[d] = 0.f;
#pragma unroll
    for (int qi = 0; qi < 64; qi++) {
        float w = s[qi]*inv;
#pragma unroll
        for (int d = 0; d < 32; d++) acc[d] += w*vsh[qi*32 + d];
    }
    int hr = ((win >> 5) << 3) + (tid >> 3), wr = ((win & 31) << 3) + (tid & 7);
    int t = (b << 16) + (hr << 8) + wr;
    float* o = g_attout + (size_t)t*256 + (h << 5);
#pragma unroll
    for (int d = 0; d < 32; d++) o[d] = acc[d];
}

// ---------------- launch ----------------
extern "C" void kernel_launch(void* const* d_in, const int* in_sizes, int n_in,
                              void* d_out, int out_size) {
    const float* x      = (const float*)d_in[0];
    const float* w_qkv  = (const float*)d_in[1];
    const float* b_qkv  = (const float*)d_in[2];
    const float* rel_pos= (const float*)d_in[3];
    const float* gn_w   = (const float*)d_in[4];
    const float* gn_b   = (const float*)d_in[5];
    const float* sq1    = (const float*)d_in[6];
    const float* sq2    = (const float*)d_in[7];
    const float* gwc    = (const float*)d_in[8];
    const float* gwc_b  = (const float*)d_in[9];
    const float* pwc1   = (const float*)d_in[10];
    const float* pwc2   = (const float*)d_in[11];
    const float* w_out  = (const float*)d_in[12];
    const float* b_out  = (const float*)d_in[13];
    float* out = (float*)d_out;

    float *p_wqkv, *p_wout, *p_wpwc1, *p_wpwc2, *p_wsq, *p_wgwc;
    cudaGetSymbolAddress((void**)&p_wqkv,  g_wqkv_t);
    cudaGetSymbolAddress((void**)&p_wout,  g_wout_t);
    cudaGetSymbolAddress((void**)&p_wpwc1, g_wpwc1_t);
    cudaGetSymbolAddress((void**)&p_wpwc2, g_wpwc2_t);
    cudaGetSymbolAddress((void**)&p_wsq,   g_wsq_t);
    cudaGetSymbolAddress((void**)&p_wgwc,  g_wgwc_t);

    cudaFuncSetAttribute(sru_win, cudaFuncAttributeMaxDynamicSharedMemorySize, 70000);

    zero_small<<<4, 256>>>();
    transpose_w<<<(768*256 + 255)/256, 256>>>(w_qkv, p_wqkv, 768, 256);
    transpose_w<<<(256*256 + 255)/256, 256>>>(w_out, p_wout, 256, 256);
    transpose_w<<<(256*64 + 255)/256, 256>>>(pwc1, p_wpwc1, 256, 64);
    transpose_w<<<(192*64 + 255)/256, 256>>>(pwc2, p_wpwc2, 192, 64);
    make_sq<<<128, 256>>>(sq1, sq2);
    make_gwc<<<(2*288*128 + 255)/256, 256>>>(gwc);
    sum_gnw<<<1, 256>>>(gn_w);

    // QKV projection (fused roll-gather A, split epilogue)
    sgemm_k<<<dim3(6, 1024, 1), 256>>>(AQKV{x}, p_wqkv, 0, EQKV{b_qkv}, 768, 256);

    // SRU on q
    gn_stats<<<512, 256>>>();
    sru_win<<<2048, 256, (64*257 + 768)*4>>>(gn_w, gn_b);

    // CRU on k
    sgemm_k<<<dim3(1, 1024, 1), 256>>>(AKtok{}, p_wsq, 0, EUL{}, 128, 256);
    sgemm_k<<<dim3(1, 1024, 2), 256>>>(AConv{}, p_wgwc, 288*128, EY1{gwc_b}, 128, 288);
    sgemm_k<<<dim3(2, 1024, 1), 256>>>(AUp{}, p_wpwc1, 0, EAddY1{}, 256, 64);
    sgemm_k<<<dim3(2, 1024, 1), 256>>>(ALow{}, p_wpwc2, 0, EY2{}, 192, 64);
    pool_kernel<<<512, 256>>>();
    softmax512<<<2, 512>>>();
    cru_combine<<<131072, 256>>>();

    // attention + output projection (with un-roll scatter)
    attn<<<dim3(1024, 8, 2), 64>>>(rel_pos);
    sgemm_k<<<dim3(2, 1024, 1), 256>>>(AAtt{}, p_wout, 0, EOut{b_out, out}, 256, 256);
}

// round 2
// speedup vs baseline: 1.1522x; 1.1522x over previous
#include <cuda_runtime.h>
#include <cuda_bf16.h>
#include <math.h>

// ---------------- problem constants ----------------
#define TTOT 131072          // B*H*W tokens (rolled coords)
#define SCALE 0.17677669529663687f
#define GN_N 1048576.0f      // 16 channels * 65536 pixels per group

typedef unsigned long long ull;

__device__ __forceinline__ ull pack2(float a, float b) {
    ull r;
    asm("mov.b64 %0, {%1, %2};" : "=l"(r) : "f"(a), "f"(b));
    return r;
}
__device__ __forceinline__ void unpack2(ull p, float& a, float& b) {
    asm("mov.b64 {%0, %1}, %2;" : "=f"(a), "=f"(b) : "l"(p));
}
__device__ __forceinline__ void ffma2(ull& d, ull a, ull b) {
    asm("fma.rn.f32x2 %0, %1, %2, %0;" : "+l"(d) : "l"(a), "l"(b));
}

// ---------------- scratch (device globals; allocation-free) ----------------
__device__ float g_qgn  [(size_t)TTOT*256]; // q path, NCHW rolled spatial
__device__ float g_ktok [(size_t)TTOT*256]; // k path, token-major [t][256]
__device__ float g_vatt [(size_t)TTOT*256]; // v, [b][win][head][p][d]
__device__ float g_qatt [(size_t)TTOT*256]; // q after SRU, same layout
__device__ float g_katt [(size_t)TTOT*256]; // k after CRU, same layout
__device__ float g_ul   [(size_t)TTOT*128]; // up(0..63) | low(64..127), token-major
__device__ float g_y1   [(size_t)TTOT*256];
__device__ float g_y2   [(size_t)TTOT*192];
__device__ float g_attout[(size_t)TTOT*256]; // attention out, token-major [t][256]
__device__ float g_wqkv_t [256*768];
__device__ float g_wsq_t  [256*128];
__device__ float g_wgwcp_t[2*352*128];   // fused gwc(288) + pwc1(64) per group
__device__ float g_wpwc2_t[64*192];
__device__ float g_wout_t [256*256];
__device__ float g_gnstats[2*16*2];
__device__ float g_pool[2*512];
__device__ float g_misc[4];

// ---------------- small utility kernels ----------------
__global__ void zero_small() {
    int i = blockIdx.x*256 + threadIdx.x;
    if (i < 1024) g_pool[i] = 0.f;
    if (i < 64)   g_gnstats[i] = 0.f;
}

// out[k*N + n] = in[n*K + k]
__global__ void transpose_w(const float* __restrict__ in, float* __restrict__ out, int N, int K) {
    int i = blockIdx.x*256 + threadIdx.x;
    if (i >= N*K) return;
    int n = i % N, k = i / N;
    out[i] = in[n*K + k];
}

// zero-padded block-diagonal squeeze weight: [K=256][N=128]
__global__ void make_sq(const float* __restrict__ sq1, const float* __restrict__ sq2) {
    int i = blockIdx.x*256 + threadIdx.x;
    if (i >= 256*128) return;
    int n = i & 127, k = i >> 7;
    float v = 0.f;
    if (n < 64)  { if (k < 128)  v = sq1[n*128 + k]; }
    else         { if (k >= 128) v = sq2[(n-64)*128 + (k-128)]; }
    g_wsq_t[i] = v;
}

// fused gwc+pwc1 weights: [z][k=0..351][n=0..127]; out channel c = z*128+n
__global__ void make_gwcp(const float* __restrict__ gwc, const float* __restrict__ pwc1) {
    int i = blockIdx.x*256 + threadIdx.x;
    if (i >= 2*352*128) return;
    int z = i / 45056, r = i % 45056;
    int k = r >> 7, n = r & 127;
    int c = z*128 + n;
    g_wgwcp_t[i] = (k < 288) ? gwc[c*288 + k] : pwc1[c*64 + (k - 288)];
}

__global__ void sum_gnw(const float* __restrict__ gn_w) {
    __shared__ float sh[256];
    sh[threadIdx.x] = gn_w[threadIdx.x];
    __syncthreads();
    for (int st = 128; st > 0; st >>= 1) {
        if (threadIdx.x < st) sh[threadIdx.x] += sh[threadIdx.x + st];
        __syncthreads();
    }
    if (threadIdx.x == 0) g_misc[0] = sh[0];
}

// ---------------- generic 128x128x16 SGEMM with packed f32x2 FMA ----------------
template<class AF, class EF>
__global__ __launch_bounds__(256) void sgemm_k(AF af, const float* __restrict__ Bt,
                                               int bstride, EF ef, int N, int K) {
    __shared__ __align__(16) float As[16][128];
    __shared__ __align__(16) float Bs[16][128];
    int z = blockIdx.z;
    const float* B = Bt + (size_t)z * bstride;
    int m0 = blockIdx.y << 7, n0 = blockIdx.x << 7;
    int tid = threadIdx.x;
    int r0 = (tid >> 4) << 3, c0 = (tid & 15) << 3;
    ull acc2[8][4];
    ull zz = pack2(0.f, 0.f);
#pragma unroll
    for (int i = 0; i < 8; i++)
#pragma unroll
        for (int j = 0; j < 4; j++) acc2[i][j] = zz;

    for (int k0 = 0; k0 < K; k0 += 16) {
#pragma unroll
        for (int i = 0; i < 8; i++) {
            int idx = (i << 8) + tid;
            int rr = idx & 127, kk = idx >> 7;
            As[kk][rr] = af(m0 + rr, k0 + kk, z);
        }
#pragma unroll
        for (int i = 0; i < 8; i++) {
            int idx = (i << 8) + tid;
            int cc = idx & 127, kk = idx >> 7;
            int n = n0 + cc;
            Bs[kk][cc] = (n < N) ? B[(size_t)(k0 + kk)*N + n] : 0.f;
        }
        __syncthreads();
#pragma unroll
        for (int kk = 0; kk < 16; kk++) {
            float4 a0 = *(const float4*)&As[kk][r0];
            float4 a1 = *(const float4*)&As[kk][r0 + 4];
            ull ad[8];
            ad[0] = pack2(a0.x, a0.x); ad[1] = pack2(a0.y, a0.y);
            ad[2] = pack2(a0.z, a0.z); ad[3] = pack2(a0.w, a0.w);
            ad[4] = pack2(a1.x, a1.x); ad[5] = pack2(a1.y, a1.y);
            ad[6] = pack2(a1.z, a1.z); ad[7] = pack2(a1.w, a1.w);
            const ull* bp = (const ull*)&Bs[kk][c0];
            ull b0 = bp[0], b1 = bp[1], b2 = bp[2], b3 = bp[3];
#pragma unroll
            for (int i = 0; i < 8; i++) {
                ffma2(acc2[i][0], ad[i], b0);
                ffma2(acc2[i][1], ad[i], b1);
                ffma2(acc2[i][2], ad[i], b2);
                ffma2(acc2[i][3], ad[i], b3);
            }
        }
        __syncthreads();
    }
#pragma unroll
    for (int i = 0; i < 8; i++) {
        int m = m0 + r0 + i;
#pragma unroll
        for (int j = 0; j < 4; j++) {
            float lo, hi;
            unpack2(acc2[i][j], lo, hi);
            int n = n0 + c0 + 2*j;
            if (n < N)     ef(m, n,     z, lo);
            if (n + 1 < N) ef(m, n + 1, z, hi);
        }
    }
}

// ---------------- A loaders ----------------
struct AQKV {
    const float* x;
    __device__ float operator()(int t, int k, int z) const {
        int b = t >> 16, pixi = t & 65535;
        int hr = pixi >> 8, wr = pixi & 255;
        return x[(size_t)((b << 8) + k)*65536 + (((hr + 4) & 255) << 8) + ((wr + 4) & 255)];
    }
};
struct AKtok {
    __device__ float operator()(int t, int k, int z) const { return g_ktok[(size_t)t*256 + k]; }
};
struct ALow {
    __device__ float operator()(int t, int k, int z) const { return g_ul[(size_t)t*128 + 64 + k]; }
};
struct AAtt {
    __device__ float operator()(int t, int k, int z) const { return g_attout[(size_t)t*256 + k]; }
};
// implicit im2col for grouped 3x3 conv over 'up' (k<288) + pwc1 input (k>=288)
struct AConvP {
    __device__ float operator()(int t, int k, int z) const {
        if (k >= 288) return g_ul[(size_t)t*128 + (k - 288)];
        int kl = k / 9;                 // 0..31
        int tap = k - kl*9;
        int kin = (z << 5) + kl;
        int dy = tap/3 - 1, dx = tap - (tap/3)*3 - 1;
        int b = t >> 16, pixi = t & 65535;
        int hr = (pixi >> 8) + dy, wr = (pixi & 255) + dx;
        if ((unsigned)hr > 255u || (unsigned)wr > 255u) return 0.f;
        return g_ul[(size_t)((b << 16) + (hr << 8) + wr)*128 + kin];
    }
};

// ---------------- epilogues ----------------
struct EQKV {
    const float* bias;
    __device__ void operator()(int t, int n, int z, float v) const {
        v += bias[n];
        int b = t >> 16, pixi = t & 65535;
        if (n < 256) {
            g_qgn[(size_t)((b << 8) + n)*65536 + pixi] = v;
        } else if (n < 512) {
            g_ktok[(size_t)t*256 + (n - 256)] = v;
        } else {
            int c = n - 512;
            int hr = pixi >> 8, wr = pixi & 255;
            int win = ((hr >> 3) << 5) + (wr >> 3);
            int p = ((hr & 7) << 3) + (wr & 7);
            g_vatt[((size_t)((b << 10) + win)*8 + (c >> 5))*2048 + p*32 + (c & 31)] = v;
        }
    }
};
struct EUL {
    __device__ void operator()(int t, int n, int z, float v) const { g_ul[(size_t)t*128 + n] = v; }
};
struct EY1 {
    const float* bias;
    __device__ void operator()(int t, int n, int z, float v) const {
        int c = (z << 7) + n;
        g_y1[(size_t)t*256 + c] = v + bias[c];
    }
};
struct EY2 {
    __device__ void operator()(int t, int n, int z, float v) const { g_y2[(size_t)t*192 + n] = v; }
};
struct EOut {
    const float* bias; float* out;
    __device__ void operator()(int t, int n, int z, float v) const {
        int b = t >> 16, pixi = t & 65535;
        int hr = pixi >> 8, wr = pixi & 255;
        out[(size_t)((b << 8) + n)*65536 + (((hr + 4) & 255) << 8) + ((wr + 4) & 255)] = v + bias[n];
    }
};

// ---------------- GroupNorm stats ----------------
__global__ void gn_stats() {
    int bx = blockIdx.x;            // 0..511 : one channel of one batch
    int b = bx >> 8, c = bx & 255;
    const float* p = g_qgn + (size_t)((b << 8) + c)*65536;
    float s = 0.f, s2 = 0.f;
    for (int i = threadIdx.x; i < 65536; i += 256) {
        float v = p[i];
        s += v; s2 += v*v;
    }
    __shared__ float sh[512];
    sh[threadIdx.x] = s; sh[256 + threadIdx.x] = s2;
    __syncthreads();
    for (int st = 128; st > 0; st >>= 1) {
        if (threadIdx.x < st) {
            sh[threadIdx.x] += sh[threadIdx.x + st];
            sh[256 + threadIdx.x] += sh[256 + threadIdx.x + st];
        }
        __syncthreads();
    }
    if (threadIdx.x == 0) {
        int g = c >> 4;
        atomicAdd(&g_gnstats[((b << 4) + g)*2],     sh[0]);
        atomicAdd(&g_gnstats[((b << 4) + g)*2 + 1], sh[256]);
    }
}

// ---------------- SRU per window ----------------
__global__ void sru_win(const float* __restrict__ gn_w, const float* __restrict__ gn_b) {
    extern __shared__ float sm[];
    float* s   = sm;                 // 64*257 floats
    float* gnA = sm + 64*257;
    float* gnB = gnA + 256;
    float* wg  = gnB + 256;
    int blk = blockIdx.x, b = blk >> 10, win = blk & 1023;
    int wy = win >> 5, wx = win & 31;
    int tid = threadIdx.x;

    if (tid < 256) {
        int c = tid, g = c >> 4;
        float mean = g_gnstats[((b << 4) + g)*2] / GN_N;
        float var  = g_gnstats[((b << 4) + g)*2 + 1] / GN_N - mean*mean;
        float rstd = rsqrtf(var + 1e-5f);
        float w = gn_w[c];
        gnA[c] = rstd * w;
        gnB[c] = gn_b[c] - mean * rstd * w;
        wg[c]  = w / g_misc[0];
    }
    const float* src = g_qgn + (size_t)b*256*65536;
    for (int idx = tid; idx < 16384; idx += 256) {
        int c = idx >> 6, p = idx & 63;
        int hr = (wy << 3) + (p >> 3), wr = (wx << 3) + (p & 7);
        s[p*257 + c] = src[(size_t)c*65536 + (hr << 8) + wr];
    }
    __syncthreads();
    for (int idx = tid; idx < 8192; idx += 256) {
        int c = idx & 127, p = idx >> 7;
        int c2 = c + 128;
        float x1 = s[p*257 + c], x2 = s[p*257 + c2];
        float gn1 = x1*gnA[c] + gnB[c];
        float gn2 = x2*gnA[c2] + gnB[c2];
        float rw1 = 1.0f/(1.0f + expf(-gn1*wg[c]));
        float rw2 = 1.0f/(1.0f + expf(-gn2*wg[c2]));
        float w11 = rw1 > 0.5f ? 1.0f : rw1, w21 = rw1 > 0.5f ? 0.0f : rw1;
        float w12 = rw2 > 0.5f ? 1.0f : rw2, w22 = rw2 > 0.5f ? 0.0f : rw2;
        s[p*257 + c]  = w11*x1 + w22*x2;
        s[p*257 + c2] = w12*x2 + w21*x1;
    }
    __syncthreads();
    float* dst = g_qatt + (size_t)blk*16384;
    for (int idx = tid; idx < 16384; idx += 256) {
        int head = idx >> 11, p = (idx >> 5) & 63, d = idx & 31;
        dst[idx] = s[p*257 + (head << 5) + d];
    }
}

// ---------------- CRU pooling / softmax / combine ----------------
__global__ void pool_kernel() {
    int t0 = blockIdx.x * 256;
    int b = t0 >> 16;
    int tid = threadIdx.x;
    float a1 = 0.f, a2 = 0.f, a3 = 0.f;
    for (int t = t0; t < t0 + 256; t++) {
        a1 += g_y1[(size_t)t*256 + tid];
        if (tid < 192) a2 += g_y2[(size_t)t*192 + tid];
        if (tid < 64)  a3 += g_ul[(size_t)t*128 + 64 + tid];
    }
    atomicAdd(&g_pool[(b << 9) + tid], a1);
    if (tid < 192) atomicAdd(&g_pool[(b << 9) + 256 + tid], a2);
    if (tid < 64)  atomicAdd(&g_pool[(b << 9) + 448 + tid], a3);
}

__global__ void softmax512() {
    int b = blockIdx.x, t = threadIdx.x;
    __shared__ float sh[512];
    float v = g_pool[(b << 9) + t] * (1.0f/65536.0f);
    sh[t] = v;
    __syncthreads();
    for (int st = 256; st > 0; st >>= 1) { if (t < st) sh[t] = fmaxf(sh[t], sh[t + st]); __syncthreads(); }
    float mx = sh[0];
    __syncthreads();
    float e = expf(v - mx);
    sh[t] = e;
    __syncthreads();
    for (int st = 256; st > 0; st >>= 1) { if (t < st) sh[t] += sh[t + st]; __syncthreads(); }
    float sum = sh[0];
    __syncthreads();
    g_pool[(b << 9) + t] = e / sum;
}

__global__ void cru_combine() {
    int i = blockIdx.x*256 + threadIdx.x;          // < TTOT*256
    int t = i >> 8, c = i & 255;
    int b = t >> 16, pixi = t & 65535;
    float y1 = g_y1[i];
    float y2v = (c < 192) ? g_y2[(size_t)t*192 + c] : g_ul[(size_t)t*128 + 64 + (c - 192)];
    float s1 = g_pool[(b << 9) + c], s2 = g_pool[(b << 9) + 256 + c];
    float v = s1*y1 + s2*y2v;
    int hr = pixi >> 8, wr = pixi & 255;
    int win = ((hr >> 3) << 5) + (wr >> 3);
    int p = ((hr & 7) << 3) + (wr & 7);
    g_katt[((size_t)((b << 10) + win)*8 + (c >> 5))*2048 + p*32 + (c & 31)] = v;
}

// ---------------- windowed attention (packed f32x2 math) ----------------
__global__ __launch_bounds__(64) void attn(const float* __restrict__ rel_pos) {
    int win = blockIdx.x, h = blockIdx.y, b = blockIdx.z;
    __shared__ __align__(16) float ksh[2048];
    __shared__ __align__(16) float vsh[2048];
    __shared__ float rp[225];
    size_t base = ((size_t)((b << 10) + win)*8 + h)*2048;
    const float* kin = g_katt + base;
    const float* vin = g_vatt + base;
    const float* qin = g_qatt + base;
    int tid = threadIdx.x;
    for (int i = tid; i < 2048; i += 64) { ksh[i] = kin[i]; vsh[i] = vin[i]; }
    for (int i = tid; i < 225; i += 64) rp[i] = rel_pos[h*225 + i];
    __syncthreads();

    ull qp[16];
#pragma unroll
    for (int d = 0; d < 16; d++) {
        float2 qv = *(const float2*)&qin[tid*32 + 2*d];
        qp[d] = pack2(qv.x, qv.y);
    }
    int ph = tid >> 3, pw = tid & 7;
    bool lr = (win >> 5) == 31, lc = (win & 31) == 31;
    ull zz = pack2(0.f, 0.f);

    float s[64];
#pragma unroll
    for (int qi = 0; qi < 64; qi++) {
        const ull* kp = (const ull*)&ksh[qi*32];
        ull dp = zz;
#pragma unroll
        for (int d = 0; d < 16; d++) ffma2(dp, qp[d], kp[d]);
        float dl, dh;
        unpack2(dp, dl, dh);
        float dot = dl + dh;
        int qh = qi >> 3, qw = qi & 7;
        float val = dot*SCALE + rp[(ph - qh + 7)*15 + (pw - qw + 7)];
        if ((lr && ((ph < 4) != (qh < 4))) || (lc && ((pw < 4) != (qw < 4)))) val = -1e30f;
        s[qi] = val;
    }
    float mx = -1e30f;
#pragma unroll
    for (int qi = 0; qi < 64; qi++) mx = fmaxf(mx, s[qi]);
    float sum = 0.f;
#pragma unroll
    for (int qi = 0; qi < 64; qi++) { s[qi] = expf(s[qi] - mx); sum += s[qi]; }
    float inv = 1.0f / sum;
    ull accp[16];
#pragma unroll
    for (int d = 0; d < 16; d++) accp[d] = zz;
#pragma unroll
    for (int qi = 0; qi < 64; qi++) {
        float w = s[qi]*inv;
        ull wd = pack2(w, w);
        const ull* vp = (const ull*)&vsh[qi*32];
#pragma unroll
        for (int d = 0; d < 16; d++) ffma2(accp[d], wd, vp[d]);
    }
    int hr = ((win >> 5) << 3) + (tid >> 3), wr = ((win & 31) << 3) + (tid & 7);
    int t = (b << 16) + (hr << 8) + wr;
    float* o = g_attout + (size_t)t*256 + (h << 5);
#pragma unroll
    for (int d = 0; d < 16; d++) {
        float lo, hi;
        unpack2(accp[d], lo, hi);
        o[2*d] = lo; o[2*d + 1] = hi;
    }
}

// ---------------- launch ----------------
extern "C" void kernel_launch(void* const* d_in, const int* in_sizes, int n_in,
                              void* d_out, int out_size) {
    const float* x      = (const float*)d_in[0];
    const float* w_qkv  = (const float*)d_in[1];
    const float* b_qkv  = (const float*)d_in[2];
    const float* rel_pos= (const float*)d_in[3];
    const float* gn_w   = (const float*)d_in[4];
    const float* gn_b   = (const float*)d_in[5];
    const float* sq1    = (const float*)d_in[6];
    const float* sq2    = (const float*)d_in[7];
    const float* gwc    = (const float*)d_in[8];
    const float* gwc_b  = (const float*)d_in[9];
    const float* pwc1   = (const float*)d_in[10];
    const float* pwc2   = (const float*)d_in[11];
    const float* w_out  = (const float*)d_in[12];
    const float* b_out  = (const float*)d_in[13];
    float* out = (float*)d_out;

    float *p_wqkv, *p_wout, *p_wpwc2, *p_wsq, *p_wgwcp;
    cudaGetSymbolAddress((void**)&p_wqkv,  g_wqkv_t);
    cudaGetSymbolAddress((void**)&p_wout,  g_wout_t);
    cudaGetSymbolAddress((void**)&p_wpwc2, g_wpwc2_t);
    cudaGetSymbolAddress((void**)&p_wsq,   g_wsq_t);
    cudaGetSymbolAddress((void**)&p_wgwcp, g_wgwcp_t);

    cudaFuncSetAttribute(sru_win, cudaFuncAttributeMaxDynamicSharedMemorySize, 70000);

    zero_small<<<4, 256>>>();
    transpose_w<<<(768*256 + 255)/256, 256>>>(w_qkv, p_wqkv, 768, 256);
    transpose_w<<<(256*256 + 255)/256, 256>>>(w_out, p_wout, 256, 256);
    transpose_w<<<(192*64 + 255)/256, 256>>>(pwc2, p_wpwc2, 192, 64);
    make_sq<<<128, 256>>>(sq1, sq2);
    make_gwcp<<<(2*352*128 + 255)/256, 256>>>(gwc, pwc1);
    sum_gnw<<<1, 256>>>(gn_w);

    // QKV projection (fused roll-gather A, split epilogue)
    sgemm_k<<<dim3(6, 1024, 1), 256>>>(AQKV{x}, p_wqkv, 0, EQKV{b_qkv}, 768, 256);

    // SRU on q
    gn_stats<<<512, 256>>>();
    sru_win<<<2048, 256, (64*257 + 768)*4>>>(gn_w, gn_b);

    // CRU on k
    sgemm_k<<<dim3(1, 1024, 1), 256>>>(AKtok{}, p_wsq, 0, EUL{}, 128, 256);
    sgemm_k<<<dim3(1, 1024, 2), 256>>>(AConvP{}, p_wgwcp, 352*128, EY1{gwc_b}, 128, 352);
    sgemm_k<<<dim3(2, 1024, 1), 256>>>(ALow{}, p_wpwc2, 0, EY2{}, 192, 64);
    pool_kernel<<<512, 256>>>();
    softmax512<<<2, 512>>>();
    cru_combine<<<131072, 256>>>();

    // attention + output projection (with un-roll scatter)
    attn<<<dim3(1024, 8, 2), 64>>>(rel_pos);
    sgemm_k<<<dim3(2, 1024, 1), 256>>>(AAtt{}, p_wout, 0, EOut{b_out, out}, 256, 256);
}

// round 3
// speedup vs baseline: 1.2572x; 1.0912x over previous
#include <cuda_runtime.h>
#include <cuda_bf16.h>
#include <math.h>

#define TTOT 131072
#define SCALE 0.17677669529663687f
#define GN_N 1048576.0f

typedef unsigned long long ull;

__device__ __forceinline__ ull pack2(float a, float b) {
    ull r; asm("mov.b64 %0, {%1, %2};" : "=l"(r) : "f"(a), "f"(b)); return r;
}
__device__ __forceinline__ void unpack2(ull p, float& a, float& b) {
    asm("mov.b64 {%0, %1}, %2;" : "=f"(a), "=f"(b) : "l"(p));
}
__device__ __forceinline__ void ffma2(ull& d, ull a, ull b) {
    asm("fma.rn.f32x2 %0, %1, %2, %0;" : "+l"(d) : "l"(a), "l"(b));
}

// ---------------- scratch ----------------
__device__ float g_q   [(size_t)TTOT*256];
__device__ float g_k   [(size_t)TTOT*256];
__device__ float g_v   [(size_t)TTOT*256];
__device__ float g_qa  [(size_t)TTOT*256];
__device__ float g_ka  [(size_t)TTOT*256];
__device__ float g_ul  [(size_t)TTOT*128];
__device__ float g_y1  [(size_t)TTOT*256];
__device__ float g_y2  [(size_t)TTOT*192];
__device__ float g_attout[(size_t)TTOT*256];
__device__ float g_wqkv_t [256*768];
__device__ float g_wsq_t  [256*128];
__device__ float g_wgwcp_t[2*352*128];
__device__ float g_wpwc2_t[64*192];
__device__ float g_wout_t [256*256];
__device__ float g_gnstats[2*16*2];
__device__ float g_pool[2*512];
__device__ float g_misc[4];

// ---------------- small utility kernels ----------------
__global__ void zero_small() {
    int i = blockIdx.x*256 + threadIdx.x;
    if (i < 1024) g_pool[i] = 0.f;
    if (i < 64)   g_gnstats[i] = 0.f;
}

__global__ void transpose_w(const float* __restrict__ in, float* __restrict__ out, int N, int K) {
    int i = blockIdx.x*256 + threadIdx.x;
    if (i >= N*K) return;
    int n = i % N, k = i / N;
    out[i] = in[n*K + k];
}

__global__ void make_sq(const float* __restrict__ sq1, const float* __restrict__ sq2) {
    int i = blockIdx.x*256 + threadIdx.x;
    if (i >= 256*128) return;
    int n = i & 127, k = i >> 7;
    float v = 0.f;
    if (n < 64)  { if (k < 128)  v = sq1[n*128 + k]; }
    else         { if (k >= 128) v = sq2[(n-64)*128 + (k-128)]; }
    g_wsq_t[i] = v;
}

__global__ void make_gwcp(const float* __restrict__ gwc, const float* __restrict__ pwc1) {
    int i = blockIdx.x*256 + threadIdx.x;
    if (i >= 2*352*128) return;
    int z = i / 45056, r = i % 45056;
    int k = r >> 7, n = r & 127;
    int c = z*128 + n;
    g_wgwcp_t[i] = (k < 288) ? gwc[c*288 + k] : pwc1[c*64 + (k - 288)];
}

__global__ void sum_gnw(const float* __restrict__ gn_w) {
    __shared__ float sh[256];
    sh[threadIdx.x] = gn_w[threadIdx.x];
    __syncthreads();
    for (int st = 128; st > 0; st >>= 1) {
        if (threadIdx.x < st) sh[threadIdx.x] += sh[threadIdx.x + st];
        __syncthreads();
    }
    if (threadIdx.x == 0) g_misc[0] = sh[0];
}

// ---------------- generic 128x128x16 SGEMM (f32x2) ----------------
template<class AF, class EF>
__global__ __launch_bounds__(256, 2) void sgemm_k(AF af, const float* __restrict__ Bt,
                                                  int bstride, EF ef, int N, int K) {
    __shared__ __align__(16) float As[16][128];
    __shared__ __align__(16) float Bs[16][128];
    int z = blockIdx.z;
    const float* B = Bt + (size_t)z * bstride;
    int m0 = blockIdx.y << 7, n0 = blockIdx.x << 7;
    int tid = threadIdx.x;
    int r0 = (tid >> 4) << 3, c0 = (tid & 15) << 3;
    ull acc2[8][4];
    ull zz = pack2(0.f, 0.f);
#pragma unroll
    for (int i = 0; i < 8; i++)
#pragma unroll
        for (int j = 0; j < 4; j++) acc2[i][j] = zz;

    for (int k0 = 0; k0 < K; k0 += 16) {
#pragma unroll
        for (int i = 0; i < 8; i++) {
            int idx = (i << 8) + tid;
            int rr = idx & 127, kk = idx >> 7;
            As[kk][rr] = af(m0 + rr, k0 + kk, z);
        }
#pragma unroll
        for (int i = 0; i < 8; i++) {
            int idx = (i << 8) + tid;
            int cc = idx & 127, kk = idx >> 7;
            int n = n0 + cc;
            Bs[kk][cc] = (n < N) ? B[(size_t)(k0 + kk)*N + n] : 0.f;
        }
        __syncthreads();
#pragma unroll
        for (int kk = 0; kk < 16; kk++) {
            float4 a0 = *(const float4*)&As[kk][r0];
            float4 a1 = *(const float4*)&As[kk][r0 + 4];
            const ull* bp = (const ull*)&Bs[kk][c0];
            ull b0 = bp[0], b1 = bp[1], b2 = bp[2], b3 = bp[3];
            float av[8] = {a0.x, a0.y, a0.z, a0.w, a1.x, a1.y, a1.z, a1.w};
#pragma unroll
            for (int i = 0; i < 8; i++) {
                ull ai = pack2(av[i], av[i]);
                ffma2(acc2[i][0], ai, b0);
                ffma2(acc2[i][1], ai, b1);
                ffma2(acc2[i][2], ai, b2);
                ffma2(acc2[i][3], ai, b3);
            }
        }
        __syncthreads();
    }
    float psum[8];
    if (EF::HAS_POOL) {
#pragma unroll
        for (int j = 0; j < 8; j++) psum[j] = 0.f;
    }
#pragma unroll
    for (int i = 0; i < 8; i++) {
        int m = m0 + r0 + i;
#pragma unroll
        for (int j = 0; j < 4; j++) {
            float lo, hi;
            unpack2(acc2[i][j], lo, hi);
            int n = n0 + c0 + 2*j;
            if (n < N)     ef(m, n,     z, lo);
            if (n + 1 < N) ef(m, n + 1, z, hi);
            if (EF::HAS_POOL) { psum[2*j] += lo; psum[2*j+1] += hi; }
        }
    }
    if (EF::HAS_POOL) {
        float* red = &As[0][0];
        __syncthreads();
#pragma unroll
        for (int j = 0; j < 8; j++) red[(tid >> 4)*128 + c0 + j] = psum[j];
        __syncthreads();
        if (tid < 128) {
            int n = n0 + tid;
            float s = 0.f;
#pragma unroll
            for (int r = 0; r < 16; r++) s += red[r*128 + tid];
            if (n < N) {
                int slot = ef.pslot(n, z, m0 >> 16);
                if (slot >= 0) atomicAdd(&g_pool[slot], s);
            }
        }
    }
}

// ---------------- A loaders ----------------
struct AQKV {
    const float* x;
    __device__ float operator()(int t, int k, int z) const {
        int b = t >> 16, pixi = t & 65535;
        int hr = pixi >> 8, wr = pixi & 255;
        return x[(size_t)((b << 8) + k)*65536 + (((hr + 4) & 255) << 8) + ((wr + 4) & 255)];
    }
};
struct AKtok {
    __device__ float operator()(int t, int k, int z) const { return g_k[(size_t)t*256 + k]; }
};
struct ALow {
    __device__ float operator()(int t, int k, int z) const { return g_ul[(size_t)t*128 + 64 + k]; }
};
struct AConvP {
    __device__ float operator()(int t, int k, int z) const {
        if (k >= 288) return g_ul[(size_t)t*128 + (k - 288)];
        int kl = k / 9;
        int tap = k - kl*9;
        int kin = (z << 5) + kl;
        int dy = tap/3 - 1, dx = tap - (tap/3)*3 - 1;
        int b = t >> 16, pixi = t & 65535;
        int hr = (pixi >> 8) + dy, wr = (pixi & 255) + dx;
        if ((unsigned)hr > 255u || (unsigned)wr > 255u) return 0.f;
        return g_ul[(size_t)((b << 16) + (hr << 8) + wr)*128 + kin];
    }
};

// ---------------- epilogues ----------------
struct EQKV {
    static constexpr bool HAS_POOL = false;
    const float* bias;
    __device__ void operator()(int t, int n, int z, float v) const {
        v += bias[n];
        if (n < 256)      g_q[(size_t)t*256 + n] = v;
        else if (n < 512) g_k[(size_t)t*256 + (n - 256)] = v;
        else              g_v[(size_t)t*256 + (n - 512)] = v;
    }
    __device__ int pslot(int n, int z, int b) const { return -1; }
};
struct EUL {
    static constexpr bool HAS_POOL = true;
    __device__ void operator()(int t, int n, int z, float v) const { g_ul[(size_t)t*128 + n] = v; }
    __device__ int pslot(int n, int z, int b) const { return n >= 64 ? (b << 9) + 448 + (n - 64) : -1; }
};
struct EY1 {
    static constexpr bool HAS_POOL = true;
    const float* bias;
    __device__ void operator()(int t, int n, int z, float v) const {
        int c = (z << 7) + n;
        g_y1[(size_t)t*256 + c] = v + bias[c];
    }
    __device__ int pslot(int n, int z, int b) const { return (b << 9) + (z << 7) + n; }
};
struct EY2 {
    static constexpr bool HAS_POOL = true;
    __device__ void operator()(int t, int n, int z, float v) const { g_y2[(size_t)t*192 + n] = v; }
    __device__ int pslot(int n, int z, int b) const { return (b << 9) + 256 + n; }
};

// EY1 pool must include its bias contribution: pooled mean of (gemm+bias).
// We add bias*65536/65536 = bias at softmax input time instead: simpler to fold here.
// (bias is added per-element in EY1 already, but psum is computed from raw acc;
//  compensate by adding bias[c] once per token count at softmax — handled below.)

// ---------------- GroupNorm stats (token-major) ----------------
__global__ void gn_stats() {
    int t0 = blockIdx.x * 512;
    int c = threadIdx.x;
    const float* p = g_q + (size_t)t0*256 + c;
    float s = 0.f, s2 = 0.f;
#pragma unroll 4
    for (int i = 0; i < 512; i++) {
        float v = p[(size_t)i*256];
        s += v; s2 += v*v;
    }
#pragma unroll
    for (int off = 8; off > 0; off >>= 1) {
        s  += __shfl_down_sync(0xffffffff, s,  off, 16);
        s2 += __shfl_down_sync(0xffffffff, s2, off, 16);
    }
    if ((c & 15) == 0) {
        int b = t0 >> 16, g = c >> 4;
        atomicAdd(&g_gnstats[((b << 4) + g)*2],     s);
        atomicAdd(&g_gnstats[((b << 4) + g)*2 + 1], s2);
    }
}

// ---------------- SRU (pure elementwise, token-major) ----------------
__global__ void sru_elem(const float* __restrict__ gn_w, const float* __restrict__ gn_b) {
    int i = blockIdx.x*256 + threadIdx.x;   // over TTOT*128
    int t = i >> 7, cp = i & 127;
    int b = t >> 16;
    int c1 = cp, c2 = cp + 128;
    float wsum = g_misc[0];
    int g1 = c1 >> 4, g2 = c2 >> 4;
    float m1 = g_gnstats[((b<<4)+g1)*2] / GN_N;
    float v1 = g_gnstats[((b<<4)+g1)*2+1] / GN_N - m1*m1;
    float m2 = g_gnstats[((b<<4)+g2)*2] / GN_N;
    float v2 = g_gnstats[((b<<4)+g2)*2+1] / GN_N - m2*m2;
    float w1c = gn_w[c1], w2c = gn_w[c2];
    float A1 = rsqrtf(v1 + 1e-5f)*w1c, B1 = gn_b[c1] - m1*rsqrtf(v1 + 1e-5f)*w1c;
    float A2 = rsqrtf(v2 + 1e-5f)*w2c, B2 = gn_b[c2] - m2*rsqrtf(v2 + 1e-5f)*w2c;
    float x1 = g_q[(size_t)t*256 + c1], x2 = g_q[(size_t)t*256 + c2];
    float rw1 = 1.0f/(1.0f + expf(-(x1*A1 + B1)*(w1c/wsum)));
    float rw2 = 1.0f/(1.0f + expf(-(x2*A2 + B2)*(w2c/wsum)));
    float w11 = rw1 > 0.5f ? 1.0f : rw1, w21 = rw1 > 0.5f ? 0.0f : rw1;
    float w12 = rw2 > 0.5f ? 1.0f : rw2, w22 = rw2 > 0.5f ? 0.0f : rw2;
    g_qa[(size_t)t*256 + c1] = w11*x1 + w22*x2;
    g_qa[(size_t)t*256 + c2] = w12*x2 + w21*x1;
}

// ---------------- softmax over pooled (with EY1-bias correction) ----------------
__global__ void softmax512(const float* __restrict__ gwc_b) {
    int b = blockIdx.x, t = threadIdx.x;
    __shared__ float sh[512];
    float v = g_pool[(b << 9) + t] * (1.0f/65536.0f);
    // EY1's pool reduction summed raw GEMM accs; y1 includes +gwc_b[c]. Add it back.
    if (t < 256) v += gwc_b[t];
    sh[t] = v;
    __syncthreads();
    for (int st = 256; st > 0; st >>= 1) { if (t < st) sh[t] = fmaxf(sh[t], sh[t + st]); __syncthreads(); }
    float mx = sh[0];
    __syncthreads();
    float e = expf(v - mx);
    sh[t] = e;
    __syncthreads();
    for (int st = 256; st > 0; st >>= 1) { if (t < st) sh[t] += sh[t + st]; __syncthreads(); }
    float sum = sh[0];
    __syncthreads();
    g_pool[(b << 9) + t] = e / sum;
}

__global__ void cru_combine() {
    int i = blockIdx.x*256 + threadIdx.x;
    int t = i >> 8, c = i & 255;
    int b = t >> 16;
    float y1 = g_y1[i];
    float y2v = (c < 192) ? g_y2[(size_t)t*192 + c] : g_ul[(size_t)t*128 + 64 + (c - 192)];
    float s1 = g_pool[(b << 9) + c], s2 = g_pool[(b << 9) + 256 + c];
    g_ka[(size_t)t*256 + c] = s1*y1 + s2*y2v;
}

// ---------------- windowed attention (token-major gather) ----------------
__global__ __launch_bounds__(64) void attn(const float* __restrict__ rel_pos) {
    int win = blockIdx.x, h = blockIdx.y, b = blockIdx.z;
    __shared__ __align__(16) float ksh[2048];
    __shared__ __align__(16) float vsh[2048];
    __shared__ float rp[225];
    int wy = win >> 5, wx = win & 31;
    int t0 = (b << 16) + (wy << 11) + (wx << 3);  // token of window origin
    int tid = threadIdx.x;
    int hb = h << 5;
    for (int i = tid; i < 2048; i += 64) {
        int p = i >> 5, d = i & 31;
        int t = t0 + ((p >> 3) << 8) + (p & 7);
        ksh[i] = g_ka[(size_t)t*256 + hb + d];
        vsh[i] = g_v [(size_t)t*256 + hb + d];
    }
    for (int i = tid; i < 225; i += 64) rp[i] = rel_pos[h*225 + i];
    __syncthreads();

    int myt = t0 + ((tid >> 3) << 8) + (tid & 7);
    ull qp[16];
#pragma unroll
    for (int d = 0; d < 16; d++) {
        float2 qv = *(const float2*)&g_qa[(size_t)myt*256 + hb + 2*d];
        qp[d] = pack2(qv.x, qv.y);
    }
    int ph = tid >> 3, pw = tid & 7;
    bool lr = wy == 31, lc = wx == 31;
    ull zz = pack2(0.f, 0.f);

    float s[64];
#pragma unroll
    for (int qi = 0; qi < 64; qi++) {
        const ull* kp = (const ull*)&ksh[qi*32];
        ull dp = zz;
#pragma unroll
        for (int d = 0; d < 16; d++) ffma2(dp, qp[d], kp[d]);
        float dl, dh;
        unpack2(dp, dl, dh);
        float dot = dl + dh;
        int qh = qi >> 3, qw = qi & 7;
        float val = dot*SCALE + rp[(ph - qh + 7)*15 + (pw - qw + 7)];
        if ((lr && ((ph < 4) != (qh < 4))) || (lc && ((pw < 4) != (qw < 4)))) val = -1e30f;
        s[qi] = val;
    }
    float mx = -1e30f;
#pragma unroll
    for (int qi = 0; qi < 64; qi++) mx = fmaxf(mx, s[qi]);
    float sum = 0.f;
#pragma unroll
    for (int qi = 0; qi < 64; qi++) { s[qi] = expf(s[qi] - mx); sum += s[qi]; }
    float inv = 1.0f / sum;
    ull accp[16];
#pragma unroll
    for (int d = 0; d < 16; d++) accp[d] = zz;
#pragma unroll
    for (int qi = 0; qi < 64; qi++) {
        float w = s[qi]*inv;
        ull wd = pack2(w, w);
        const ull* vp = (const ull*)&vsh[qi*32];
#pragma unroll
        for (int d = 0; d < 16; d++) ffma2(accp[d], wd, vp[d]);
    }
    float* o = g_attout + (size_t)myt*256 + hb;
#pragma unroll
    for (int d = 0; d < 16; d++) {
        float lo, hi;
        unpack2(accp[d], lo, hi);
        o[2*d] = lo; o[2*d + 1] = hi;
    }
}

// ---------------- out-projection GEMM with staged NCHW writes ----------------
__global__ __launch_bounds__(256, 2) void sgemm_out(const float* __restrict__ Bt,
                                                    const float* __restrict__ bias,
                                                    float* __restrict__ out) {
    __shared__ __align__(16) float As[16][128];
    __shared__ __align__(16) float Bs[16][128];
    __shared__ float stage[32][129];
    int m0 = blockIdx.y << 7, n0 = blockIdx.x << 7;
    int tid = threadIdx.x;
    int r0 = (tid >> 4) << 3, c0 = (tid & 15) << 3;
    ull acc2[8][4];
    ull zz = pack2(0.f, 0.f);
#pragma unroll
    for (int i = 0; i < 8; i++)
#pragma unroll
        for (int j = 0; j < 4; j++) acc2[i][j] = zz;

    for (int k0 = 0; k0 < 256; k0 += 16) {
#pragma unroll
        for (int i = 0; i < 8; i++) {
            int idx = (i << 8) + tid;
            int rr = idx & 127, kk = idx >> 7;
            As[kk][rr] = g_attout[(size_t)(m0 + rr)*256 + k0 + kk];
        }
#pragma unroll
        for (int i = 0; i < 8; i++) {
            int idx = (i << 8) + tid;
            int cc = idx & 127, kk = idx >> 7;
            Bs[kk][cc] = Bt[(size_t)(k0 + kk)*256 + n0 + cc];
        }
        __syncthreads();
#pragma unroll
        for (int kk = 0; kk < 16; kk++) {
            float4 a0 = *(const float4*)&As[kk][r0];
            float4 a1 = *(const float4*)&As[kk][r0 + 4];
            const ull* bp = (const ull*)&Bs[kk][c0];
            ull b0 = bp[0], b1 = bp[1], b2 = bp[2], b3 = bp[3];
            float av[8] = {a0.x, a0.y, a0.z, a0.w, a1.x, a1.y, a1.z, a1.w};
#pragma unroll
            for (int i = 0; i < 8; i++) {
                ull ai = pack2(av[i], av[i]);
                ffma2(acc2[i][0], ai, b0);
                ffma2(acc2[i][1], ai, b1);
                ffma2(acc2[i][2], ai, b2);
                ffma2(acc2[i][3], ai, b3);
            }
        }
        __syncthreads();
    }
#pragma unroll
    for (int chunk = 0; chunk < 4; chunk++) {
        if ((r0 >> 5) == chunk) {
            int rb = r0 & 31;
#pragma unroll
            for (int i = 0; i < 8; i++)
#pragma unroll
                for (int j = 0; j < 4; j++) {
                    float lo, hi;
                    unpack2(acc2[i][j], lo, hi);
                    stage[rb + i][c0 + 2*j]     = lo;
                    stage[rb + i][c0 + 2*j + 1] = hi;
                }
        }
        __syncthreads();
        int lane = tid & 31;
        int m = m0 + (chunk << 5) + lane;
        int b = m >> 16, pixi = m & 65535;
        int hr = pixi >> 8, wr = pixi & 255;
        size_t pbase = (size_t)(((hr + 4) & 255) << 8) + ((wr + 4) & 255);
        for (int nl = tid >> 5; nl < 128; nl += 8) {
            int n = n0 + nl;
            out[(size_t)((b << 8) + n)*65536 + pbase] = stage[lane][nl] + bias[n];
        }
        __syncthreads();
    }
}

// ---------------- launch ----------------
extern "C" void kernel_launch(void* const* d_in, const int* in_sizes, int n_in,
                              void* d_out, int out_size) {
    const float* x      = (const float*)d_in[0];
    const float* w_qkv  = (const float*)d_in[1];
    const float* b_qkv  = (const float*)d_in[2];
    const float* rel_pos= (const float*)d_in[3];
    const float* gn_w   = (const float*)d_in[4];
    const float* gn_b   = (const float*)d_in[5];
    const float* sq1    = (const float*)d_in[6];
    const float* sq2    = (const float*)d_in[7];
    const float* gwc    = (const float*)d_in[8];
    const float* gwc_b  = (const float*)d_in[9];
    const float* pwc1   = (const float*)d_in[10];
    const float* pwc2   = (const float*)d_in[11];
    const float* w_out  = (const float*)d_in[12];
    const float* b_out  = (const float*)d_in[13];
    float* out = (float*)d_out;

    float *p_wqkv, *p_wout, *p_wpwc2, *p_wsq, *p_wgwcp;
    cudaGetSymbolAddress((void**)&p_wqkv,  g_wqkv_t);
    cudaGetSymbolAddress((void**)&p_wout,  g_wout_t);
    cudaGetSymbolAddress((void**)&p_wpwc2, g_wpwc2_t);
    cudaGetSymbolAddress((void**)&p_wsq,   g_wsq_t);
    cudaGetSymbolAddress((void**)&p_wgwcp, g_wgwcp_t);

    zero_small<<<4, 256>>>();
    transpose_w<<<(768*256 + 255)/256, 256>>>(w_qkv, p_wqkv, 768, 256);
    transpose_w<<<(256*256 + 255)/256, 256>>>(w_out, p_wout, 256, 256);
    transpose_w<<<(192*64 + 255)/256, 256>>>(pwc2, p_wpwc2, 192, 64);
    make_sq<<<128, 256>>>(sq1, sq2);
    make_gwcp<<<(2*352*128 + 255)/256, 256>>>(gwc, pwc1);
    sum_gnw<<<1, 256>>>(gn_w);

    sgemm_k<<<dim3(6, 1024, 1), 256>>>(AQKV{x}, p_wqkv, 0, EQKV{b_qkv}, 768, 256);

    gn_stats<<<256, 256>>>();
    sru_elem<<<65536, 256>>>(gn_w, gn_b);

    sgemm_k<<<dim3(1, 1024, 1), 256>>>(AKtok{}, p_wsq, 0, EUL{}, 128, 256);
    sgemm_k<<<dim3(1, 1024, 2), 256>>>(AConvP{}, p_wgwcp, 352*128, EY1{gwc_b}, 128, 352);
    sgemm_k<<<dim3(2, 1024, 1), 256>>>(ALow{}, p_wpwc2, 0, EY2{}, 192, 64);
    softmax512<<<2, 512>>>(gwc_b);
    cru_combine<<<131072, 256>>>();

    attn<<<dim3(1024, 8, 2), 64>>>(rel_pos);
    sgemm_out<<<dim3(2, 1024), 256>>>(p_wout, b_out, out);
}